// round 4
// baseline (speedup 1.0000x reference)
#include <cuda_runtime.h>
#include <cuda_fp16.h>

// Problem constants (fixed by dataset)
#define BB 64
#define NN 50000
#define EE 1600000
#define LL 20
#define BN_EPS 1e-5f

#define SCAN_BLK 1024
#define NBLOCKS_SCAN ((NN + SCAN_BLK - 1) / SCAN_BLK)   // 49

// ---------------- scratch (static device globals; no allocation) ----------------
__device__ __half g_xT[(size_t)NN * BB];     // x transposed [N, B] fp16   6.4 MB
__device__ float  g_xhT[(size_t)NN * BB];    // x_hat transposed [N, B]   12.8 MB
__device__ int    g_counts[NN];
__device__ int    g_offsets[NN];             // exclusive scan; mutated to "ends"
__device__ int    g_blocksum[NBLOCKS_SCAN];
__device__ int    g_blockoff[NBLOCKS_SCAN];
__device__ int4   g_csr[EE];                 // {src, alpha_bits, bias_bits, 0}

// ---------------- kernels ----------------

// fused: x [B,N] fp32 -> g_xT [N,B] fp16, zero counts, init pred
__global__ void transpose_kernel(const float* __restrict__ x,
                                 const float* __restrict__ b_lin,
                                 float* __restrict__ pred) {
    __shared__ float tile[64][33];
    const int n0 = blockIdx.x * 32;
    const int tid = threadIdx.y * 32 + threadIdx.x;
    int n = n0 + threadIdx.x;
    #pragma unroll
    for (int h = 0; h < 2; h++) {
        int b = h * 32 + threadIdx.y;
        if (n < NN) tile[b][threadIdx.x] = x[(size_t)b * NN + n];
    }
    if (threadIdx.y == 0 && n < NN) g_counts[n] = 0;
    if (blockIdx.x == 0) {
        for (int i = tid; i < BB * LL; i += 1024) pred[i] = b_lin[i % LL];
    }
    __syncthreads();
    int nn = n0 + threadIdx.y;
    if (nn < NN) {
        float lo = tile[2 * threadIdx.x    ][threadIdx.y];
        float hi = tile[2 * threadIdx.x + 1][threadIdx.y];
        ((half2*)g_xT)[(size_t)nn * 32 + threadIdx.x] = __floats2half2_rn(lo, hi);
    }
}

// histogram of dst (8 edges / thread, vectorized)
__global__ void hist_kernel(const int* __restrict__ dst) {
    int i = blockIdx.x * blockDim.x + threadIdx.x;
    const int4* d4 = (const int4*)dst;
    if (2 * i + 1 < EE / 4) {
        int4 a = __ldg(&d4[2 * i]);
        int4 b = __ldg(&d4[2 * i + 1]);
        atomicAdd(&g_counts[a.x], 1);
        atomicAdd(&g_counts[a.y], 1);
        atomicAdd(&g_counts[a.z], 1);
        atomicAdd(&g_counts[a.w], 1);
        atomicAdd(&g_counts[b.x], 1);
        atomicAdd(&g_counts[b.y], 1);
        atomicAdd(&g_counts[b.z], 1);
        atomicAdd(&g_counts[b.w], 1);
    }
}

__device__ __forceinline__ int warp_incl_scan(int v, int lane) {
    #pragma unroll
    for (int off = 1; off < 32; off <<= 1) {
        int t = __shfl_up_sync(0xFFFFFFFFu, v, off);
        if (lane >= off) v += t;
    }
    return v;
}

// phase 1: per-block exclusive scan of counts; emit block totals
__global__ __launch_bounds__(SCAN_BLK) void scan_local_kernel() {
    __shared__ int warp_tot[32];
    int i = blockIdx.x * SCAN_BLK + threadIdx.x;
    int lane = threadIdx.x & 31, wid = threadIdx.x >> 5;
    int v = (i < NN) ? g_counts[i] : 0;
    int incl = warp_incl_scan(v, lane);
    if (lane == 31) warp_tot[wid] = incl;
    __syncthreads();
    if (wid == 0) {
        int w = warp_tot[lane];
        warp_tot[lane] = warp_incl_scan(w, lane) - w;
    }
    __syncthreads();
    int excl = warp_tot[wid] + incl - v;
    if (i < NN) g_offsets[i] = excl;
    if (threadIdx.x == SCAN_BLK - 1) g_blocksum[blockIdx.x] = warp_tot[wid] + incl;
}

// phase 2: scan the 49 block totals
__global__ void scan_blocks_kernel() {
    __shared__ int sd[64];
    int tid = threadIdx.x;
    int v = (tid < NBLOCKS_SCAN) ? g_blocksum[tid] : 0;
    sd[tid] = v;
    __syncthreads();
    #pragma unroll
    for (int off = 1; off < 64; off <<= 1) {
        int t = (tid >= off) ? sd[tid - off] : 0;
        __syncthreads();
        sd[tid] += t;
        __syncthreads();
    }
    if (tid < NBLOCKS_SCAN) g_blockoff[tid] = sd[tid] - v;
}

// phase 3: add block offsets
__global__ __launch_bounds__(SCAN_BLK) void scan_add_kernel() {
    int i = blockIdx.x * SCAN_BLK + threadIdx.x;
    if (i < NN) g_offsets[i] += g_blockoff[blockIdx.x];
}

// bucket-scatter 16B edge records (4 edges / thread)
__global__ void scatter_kernel(const int* __restrict__ src, const int* __restrict__ dst,
                               const float* __restrict__ alpha, const float* __restrict__ bias) {
    int i = blockIdx.x * blockDim.x + threadIdx.x;
    if (i < EE / 4) {
        int4   s = ((const int4*)src)[i];
        int4   d = ((const int4*)dst)[i];
        float4 a = ((const float4*)alpha)[i];
        float4 b = ((const float4*)bias)[i];
        int p;
        p = atomicAdd(&g_offsets[d.x], 1);
        g_csr[p] = make_int4(s.x, __float_as_int(a.x), __float_as_int(b.x), 0);
        p = atomicAdd(&g_offsets[d.y], 1);
        g_csr[p] = make_int4(s.y, __float_as_int(a.y), __float_as_int(b.y), 0);
        p = atomicAdd(&g_offsets[d.z], 1);
        g_csr[p] = make_int4(s.z, __float_as_int(a.z), __float_as_int(b.z), 0);
        p = atomicAdd(&g_offsets[d.w], 1);
        g_csr[p] = make_int4(s.w, __float_as_int(a.w), __float_as_int(b.w), 0);
    }
}

__device__ __forceinline__ float warp_sum(float v) {
    #pragma unroll
    for (int m = 16; m; m >>= 1) v += __shfl_xor_sync(0xFFFFFFFFu, v, m);
    return v;
}

// one warp per node: coalesced record loads + shuffle-broadcast, high-MLP gathers
__global__ __launch_bounds__(1024) void aggregate_kernel(const float* __restrict__ gamma,
                                                         const float* __restrict__ beta,
                                                         float* __restrict__ bn_out) {
    __shared__ float sbn[64][33];
    const int warpId = threadIdx.x >> 5;
    const int lane   = threadIdx.x & 31;
    const int n0 = blockIdx.x * 32;
    const int n  = n0 + warpId;

    if (n < NN) {
        const int end = g_offsets[n];          // mutated to end pointer by scatter
        const int cnt = g_counts[n];
        const int beg = end - cnt;
        float2 acc = make_float2(0.f, 0.f);
        float  sb  = 0.f;
        const half2* __restrict__ xT2 = (const half2*)g_xT;

        for (int base = beg; base < end; base += 32) {
            const int m = end - base;          // >=1; may exceed 32 (clamped by k<32)
            // lane-parallel coalesced record load (one 512B transaction per warp)
            int4 r = make_int4(0, 0, 0, 0);
            if (lane < m) r = __ldg(&g_csr[base + lane]);
            sb += __int_as_float(r.z);         // lane-local bias; reduced once at end
            #pragma unroll
            for (int k = 0; k < 32; k++) {
                if (k < m) {
                    int   s = __shfl_sync(0xFFFFFFFFu, r.x, k);
                    float a = __int_as_float(__shfl_sync(0xFFFFFFFFu, r.y, k));
                    float2 vf = __half22float2(xT2[(size_t)s * 32 + lane]);
                    acc.x = fmaf(a, vf.x, acc.x);
                    acc.y = fmaf(a, vf.y, acc.y);
                }
            }
        }
        sb = warp_sum(sb);                     // total per-node bias sum

        float invc = 1.0f / (float)(cnt > 1 ? cnt : 1);
        float2 xh = make_float2((acc.x + sb) * invc, (acc.y + sb) * invc);
        ((float2*)g_xhT)[(size_t)n * 32 + lane] = xh;

        float2 o = make_float2(tanhf(xh.x), tanhf(xh.y));
        float mu  = warp_sum(o.x + o.y) * (1.0f / 64.0f);
        float ex2 = warp_sum(o.x * o.x + o.y * o.y) * (1.0f / 64.0f);
        float var = ex2 - mu * mu;
        float rstd = rsqrtf(var + BN_EPS);
        float g  = gamma[n] * rstd;
        float be = beta[n];
        sbn[2 * lane    ][warpId] = (o.x - mu) * g + be;
        sbn[2 * lane + 1][warpId] = (o.y - mu) * g + be;
    }
    __syncthreads();
    #pragma unroll
    for (int r = threadIdx.x; r < 64 * 32; r += 1024) {
        int b = r >> 5, c = r & 31;
        int nn = n0 + c;
        if (nn < NN) bn_out[(size_t)b * NN + nn] = sbn[b][c];
    }
}

// pred[b,l] += sum_n x_hatT[n,b] * W[l,n]   (128 nodes per block)
__global__ __launch_bounds__(1024) void gemm_kernel(const float* __restrict__ W,
                                                    float* __restrict__ pred) {
    __shared__ float xtile[128 * 64];   // 32 KB
    __shared__ float wtile[LL * 128];   // 10 KB
    const int n0  = blockIdx.x * 128;
    const int rem = min(128, NN - n0);
    const int tid = threadIdx.x;

    for (int idx = tid; idx < 128 * 64; idx += 1024)
        xtile[idx] = (idx < rem * 64) ? g_xhT[(size_t)n0 * 64 + idx] : 0.0f;
    for (int idx = tid; idx < LL * 128; idx += 1024) {
        int l = idx >> 7, nn = idx & 127;
        wtile[idx] = (nn < rem) ? W[(size_t)l * NN + n0 + nn] : 0.0f;
    }
    __syncthreads();

    if (tid < BB / 2 * LL) {           // 640 threads
        int l = tid % LL, b = tid / LL;
        float a0 = 0.f, a1 = 0.f;
        #pragma unroll 8
        for (int nn = 0; nn < 128; ++nn) {
            float w = wtile[l * 128 + nn];
            a0 = fmaf(xtile[nn * 64 + b],      w, a0);
            a1 = fmaf(xtile[nn * 64 + b + 32], w, a1);
        }
        atomicAdd(&pred[b * LL + l],        a0);
        atomicAdd(&pred[(b + 32) * LL + l], a1);
    }
}

// ---------------- launch ----------------
extern "C" void kernel_launch(void* const* d_in, const int* in_sizes, int n_in,
                              void* d_out, int out_size) {
    const float* x     = (const float*)d_in[0];
    const int*   eidx  = (const int*)  d_in[1];
    const float* alpha = (const float*)d_in[2];
    const float* bias  = (const float*)d_in[3];
    const float* W     = (const float*)d_in[4];
    const float* b_lin = (const float*)d_in[5];
    const float* gamma = (const float*)d_in[6];
    const float* beta  = (const float*)d_in[7];

    const int* src = eidx;
    const int* dst = eidx + EE;

    float* pred   = (float*)d_out;              // [B, L] first
    float* bn_out = (float*)d_out + BB * LL;    // then [B, N]

    {
        dim3 blk(32, 32), grd((NN + 31) / 32, 1);
        transpose_kernel<<<grd, blk>>>(x, b_lin, pred);
    }
    hist_kernel<<<(EE / 8 + 255) / 256, 256>>>(dst);
    scan_local_kernel<<<NBLOCKS_SCAN, SCAN_BLK>>>();
    scan_blocks_kernel<<<1, 64>>>();
    scan_add_kernel<<<NBLOCKS_SCAN, SCAN_BLK>>>();
    scatter_kernel<<<(EE / 4 + 255) / 256, 256>>>(src, dst, alpha, bias);
    aggregate_kernel<<<(NN + 31) / 32, 1024>>>(gamma, beta, bn_out);
    gemm_kernel<<<(NN + 127) / 128, 1024>>>(W, pred);
}

// round 5
// speedup vs baseline: 1.2238x; 1.2238x over previous
#include <cuda_runtime.h>

// Problem constants (fixed by dataset)
#define BB 64
#define NN 50000
#define EE 1600000
#define LL 20
#define BN_EPS 1e-5f

#define SCAN_BLK 1024
#define NBLOCKS_SCAN ((NN + SCAN_BLK - 1) / SCAN_BLK)   // 49

#define T_BLOCKS ((NN + 31) / 32)                       // transpose blocks: 1563
#define H_BLOCKS ((EE / 8 + 1023) / 1024)               // hist blocks (1024 thr, 8 edges/thr): 196

// ---------------- scratch (static device globals; no allocation) ----------------
__device__ float  g_xT[(size_t)NN * BB];     // x transposed [N, B]      12.8 MB
__device__ float  g_xhT[(size_t)NN * BB];    // x_hat transposed [N, B]  12.8 MB
__device__ int    g_counts[NN];
__device__ int    g_offsets[NN];             // exclusive scan; mutated to "ends"
__device__ int    g_blocksum[NBLOCKS_SCAN];
__device__ int4   g_csr[EE];                 // {src, alpha_bits, bias_bits, 0}

// ---------------- kernels ----------------

// fused: [blocks 0..T_BLOCKS) transpose x [B,N] -> g_xT [N,B] (+ pred init);
//        [blocks T_BLOCKS..)  histogram of dst (counts pre-zeroed by memset node)
__global__ void transpose_hist_kernel(const float* __restrict__ x,
                                      const int* __restrict__ dst,
                                      const float* __restrict__ b_lin,
                                      float* __restrict__ pred) {
    const int tid = threadIdx.y * 32 + threadIdx.x;
    if (blockIdx.x < T_BLOCKS) {
        __shared__ float tile[64][33];
        const int n0 = blockIdx.x * 32;
        int n = n0 + threadIdx.x;
        #pragma unroll
        for (int h = 0; h < 2; h++) {
            int b = h * 32 + threadIdx.y;
            if (n < NN) tile[b][threadIdx.x] = x[(size_t)b * NN + n];
        }
        if (blockIdx.x == 0) {
            for (int i = tid; i < BB * LL; i += 1024) pred[i] = b_lin[i % LL];
        }
        __syncthreads();
        int nn = n0 + threadIdx.y;
        if (nn < NN) {
            float lo = tile[2 * threadIdx.x    ][threadIdx.y];
            float hi = tile[2 * threadIdx.x + 1][threadIdx.y];
            ((float2*)g_xT)[(size_t)nn * 32 + threadIdx.x] = make_float2(lo, hi);
        }
    } else {
        int i = (blockIdx.x - T_BLOCKS) * 1024 + tid;   // 8 edges per thread
        const int4* d4 = (const int4*)dst;
        if (2 * i + 1 < EE / 4) {
            int4 a = __ldg(&d4[2 * i]);
            int4 b = __ldg(&d4[2 * i + 1]);
            atomicAdd(&g_counts[a.x], 1);
            atomicAdd(&g_counts[a.y], 1);
            atomicAdd(&g_counts[a.z], 1);
            atomicAdd(&g_counts[a.w], 1);
            atomicAdd(&g_counts[b.x], 1);
            atomicAdd(&g_counts[b.y], 1);
            atomicAdd(&g_counts[b.z], 1);
            atomicAdd(&g_counts[b.w], 1);
        }
    }
}

__device__ __forceinline__ int warp_incl_scan(int v, int lane) {
    #pragma unroll
    for (int off = 1; off < 32; off <<= 1) {
        int t = __shfl_up_sync(0xFFFFFFFFu, v, off);
        if (lane >= off) v += t;
    }
    return v;
}

__device__ __forceinline__ int warp_sum_i(int v) {
    #pragma unroll
    for (int m = 16; m; m >>= 1) v += __shfl_xor_sync(0xFFFFFFFFu, v, m);
    return v;
}

// phase 1: per-block exclusive scan of counts; emit block totals
__global__ __launch_bounds__(SCAN_BLK) void scan_local_kernel() {
    __shared__ int warp_tot[32];
    int i = blockIdx.x * SCAN_BLK + threadIdx.x;
    int lane = threadIdx.x & 31, wid = threadIdx.x >> 5;
    int v = (i < NN) ? g_counts[i] : 0;
    int incl = warp_incl_scan(v, lane);
    if (lane == 31) warp_tot[wid] = incl;
    __syncthreads();
    if (wid == 0) {
        int w = warp_tot[lane];
        warp_tot[lane] = warp_incl_scan(w, lane) - w;
    }
    __syncthreads();
    int excl = warp_tot[wid] + incl - v;
    if (i < NN) g_offsets[i] = excl;
    if (threadIdx.x == SCAN_BLK - 1) g_blocksum[blockIdx.x] = warp_tot[wid] + incl;
}

// phase 2: add block offsets (each block warp-reduces the 49 block sums itself)
__global__ __launch_bounds__(SCAN_BLK) void scan_add_kernel() {
    __shared__ int s_off;
    if (threadIdx.x < 32) {
        int v = 0;
        for (int i = threadIdx.x; i < NBLOCKS_SCAN; i += 32)
            if (i < blockIdx.x) v += g_blocksum[i];
        v = warp_sum_i(v);
        if (threadIdx.x == 0) s_off = v;
    }
    __syncthreads();
    int i = blockIdx.x * SCAN_BLK + threadIdx.x;
    if (i < NN) g_offsets[i] += s_off;
}

// bucket-scatter 16B edge records (4 edges / thread)
__global__ void scatter_kernel(const int* __restrict__ src, const int* __restrict__ dst,
                               const float* __restrict__ alpha, const float* __restrict__ bias) {
    int i = blockIdx.x * blockDim.x + threadIdx.x;
    if (i < EE / 4) {
        int4   s = ((const int4*)src)[i];
        int4   d = ((const int4*)dst)[i];
        float4 a = ((const float4*)alpha)[i];
        float4 b = ((const float4*)bias)[i];
        int p;
        p = atomicAdd(&g_offsets[d.x], 1);
        g_csr[p] = make_int4(s.x, __float_as_int(a.x), __float_as_int(b.x), 0);
        p = atomicAdd(&g_offsets[d.y], 1);
        g_csr[p] = make_int4(s.y, __float_as_int(a.y), __float_as_int(b.y), 0);
        p = atomicAdd(&g_offsets[d.z], 1);
        g_csr[p] = make_int4(s.z, __float_as_int(a.z), __float_as_int(b.z), 0);
        p = atomicAdd(&g_offsets[d.w], 1);
        g_csr[p] = make_int4(s.w, __float_as_int(a.w), __float_as_int(b.w), 0);
    }
}

__device__ __forceinline__ float warp_sum(float v) {
    #pragma unroll
    for (int m = 16; m; m >>= 1) v += __shfl_xor_sync(0xFFFFFFFFu, v, m);
    return v;
}

// one warp per node; 16 nodes/block. Records staged in smem (coalesced) so the
// gather address chain reads LDS (29cyc) not L2 (234cyc); unroll-4 gathers for MLP.
__global__ __launch_bounds__(512) void aggregate_kernel(const float* __restrict__ gamma,
                                                        const float* __restrict__ beta,
                                                        float* __restrict__ bn_out) {
    __shared__ int4  srec[16][32];
    __shared__ float sbn[64][17];
    const int warpId = threadIdx.x >> 5;
    const int lane   = threadIdx.x & 31;
    const int n0 = blockIdx.x * 16;
    const int n  = n0 + warpId;

    if (n < NN) {
        const int end = g_offsets[n];          // mutated to end pointer by scatter
        const int cnt = g_counts[n];
        const int beg = end - cnt;
        float2 acc = make_float2(0.f, 0.f);
        float  sb  = 0.f;
        const float2* __restrict__ xT2 = (const float2*)g_xT;

        for (int base = beg; base < end; base += 32) {
            int mm = end - base; if (mm > 32) mm = 32;
            if (lane < mm) {
                int4 r = __ldg(&g_csr[base + lane]);
                srec[warpId][lane] = r;
                sb += __int_as_float(r.z);     // lane-local bias
            }
            __syncwarp();
            int k = 0;
            for (; k + 4 <= mm; k += 4) {
                int4 r0 = srec[warpId][k];
                int4 r1 = srec[warpId][k + 1];
                int4 r2 = srec[warpId][k + 2];
                int4 r3 = srec[warpId][k + 3];
                float2 v0 = xT2[(size_t)r0.x * 32 + lane];
                float2 v1 = xT2[(size_t)r1.x * 32 + lane];
                float2 v2 = xT2[(size_t)r2.x * 32 + lane];
                float2 v3 = xT2[(size_t)r3.x * 32 + lane];
                float a0 = __int_as_float(r0.y), a1 = __int_as_float(r1.y);
                float a2 = __int_as_float(r2.y), a3 = __int_as_float(r3.y);
                acc.x = fmaf(a0, v0.x, acc.x);  acc.y = fmaf(a0, v0.y, acc.y);
                acc.x = fmaf(a1, v1.x, acc.x);  acc.y = fmaf(a1, v1.y, acc.y);
                acc.x = fmaf(a2, v2.x, acc.x);  acc.y = fmaf(a2, v2.y, acc.y);
                acc.x = fmaf(a3, v3.x, acc.x);  acc.y = fmaf(a3, v3.y, acc.y);
            }
            for (; k < mm; ++k) {
                int4 r = srec[warpId][k];
                float2 v = xT2[(size_t)r.x * 32 + lane];
                float a = __int_as_float(r.y);
                acc.x = fmaf(a, v.x, acc.x);
                acc.y = fmaf(a, v.y, acc.y);
            }
            __syncwarp();
        }
        sb = warp_sum(sb);                     // per-node bias total

        float invc = 1.0f / (float)(cnt > 1 ? cnt : 1);
        float2 xh = make_float2((acc.x + sb) * invc, (acc.y + sb) * invc);
        ((float2*)g_xhT)[(size_t)n * 32 + lane] = xh;

        float2 o = make_float2(tanhf(xh.x), tanhf(xh.y));
        float mu  = warp_sum(o.x + o.y) * (1.0f / 64.0f);
        float ex2 = warp_sum(o.x * o.x + o.y * o.y) * (1.0f / 64.0f);
        float var = ex2 - mu * mu;
        float rstd = rsqrtf(var + BN_EPS);
        float g  = gamma[n] * rstd;
        float be = beta[n];
        sbn[2 * lane    ][warpId] = (o.x - mu) * g + be;
        sbn[2 * lane + 1][warpId] = (o.y - mu) * g + be;
    }
    __syncthreads();
    #pragma unroll
    for (int r = threadIdx.x; r < 64 * 16; r += 512) {
        int b = r >> 4, c = r & 15;
        int nn = n0 + c;
        if (nn < NN) bn_out[(size_t)b * NN + nn] = sbn[b][c];
    }
}

// pred[b,l] += sum_n x_hatT[n,b] * W[l,n]   (128 nodes per block)
__global__ __launch_bounds__(1024) void gemm_kernel(const float* __restrict__ W,
                                                    float* __restrict__ pred) {
    __shared__ float xtile[128 * 64];   // 32 KB
    __shared__ float wtile[LL * 128];   // 10 KB
    const int n0  = blockIdx.x * 128;
    const int rem = min(128, NN - n0);
    const int tid = threadIdx.x;

    for (int idx = tid; idx < 128 * 64; idx += 1024)
        xtile[idx] = (idx < rem * 64) ? g_xhT[(size_t)n0 * 64 + idx] : 0.0f;
    for (int idx = tid; idx < LL * 128; idx += 1024) {
        int l = idx >> 7, nn = idx & 127;
        wtile[idx] = (nn < rem) ? W[(size_t)l * NN + n0 + nn] : 0.0f;
    }
    __syncthreads();

    if (tid < BB / 2 * LL) {           // 640 threads
        int l = tid % LL, b = tid / LL;
        float a0 = 0.f, a1 = 0.f;
        #pragma unroll 8
        for (int nn = 0; nn < 128; ++nn) {
            float w = wtile[l * 128 + nn];
            a0 = fmaf(xtile[nn * 64 + b],      w, a0);
            a1 = fmaf(xtile[nn * 64 + b + 32], w, a1);
        }
        atomicAdd(&pred[b * LL + l],        a0);
        atomicAdd(&pred[(b + 32) * LL + l], a1);
    }
}

// ---------------- launch ----------------
extern "C" void kernel_launch(void* const* d_in, const int* in_sizes, int n_in,
                              void* d_out, int out_size) {
    const float* x     = (const float*)d_in[0];
    const int*   eidx  = (const int*)  d_in[1];
    const float* alpha = (const float*)d_in[2];
    const float* bias  = (const float*)d_in[3];
    const float* W     = (const float*)d_in[4];
    const float* b_lin = (const float*)d_in[5];
    const float* gamma = (const float*)d_in[6];
    const float* beta  = (const float*)d_in[7];

    const int* src = eidx;
    const int* dst = eidx + EE;

    float* pred   = (float*)d_out;              // [B, L] first
    float* bn_out = (float*)d_out + BB * LL;    // then [B, N]

    void* counts_ptr = nullptr;
    cudaGetSymbolAddress(&counts_ptr, g_counts);
    cudaMemsetAsync(counts_ptr, 0, NN * sizeof(int));

    {
        dim3 blk(32, 32), grd(T_BLOCKS + H_BLOCKS, 1);
        transpose_hist_kernel<<<grd, blk>>>(x, dst, b_lin, pred);
    }
    scan_local_kernel<<<NBLOCKS_SCAN, SCAN_BLK>>>();
    scan_add_kernel<<<NBLOCKS_SCAN, SCAN_BLK>>>();
    scatter_kernel<<<(EE / 4 + 255) / 256, 256>>>(src, dst, alpha, bias);
    aggregate_kernel<<<(NN + 15) / 16, 512>>>(gamma, beta, bn_out);
    gemm_kernel<<<(NN + 127) / 128, 1024>>>(W, pred);
}